// round 7
// baseline (speedup 1.0000x reference)
#include <cuda_runtime.h>
#include <math.h>

#define NB 8
#define NJ 17
#define NV 64
#define NPAIR (NB * NJ)             // 136
#define VOX (NV * NV * NV)          // 262144 elems = 1 MiB per pair
#define SPLIT 8
#define NBLOCKS (NPAIR * SPLIT)     // 1088  (single wave @ 8 blocks/SM on 148 SMs)
#define THREADS 256
#define CHUNK (VOX / SPLIT)         // 32768 elements per block
#define ITERS (CHUNK / 4 / THREADS) // 32 float4 per thread

__device__ float        g_partials[NBLOCKS];
__device__ float        g_loss = 0.0f;
__device__ unsigned int g_pairs_done = 0;

__device__ __forceinline__ int grid_idx(float l, float c) {
    float norm = (l - c) * (1.0f / 1000.0f);        // box_range = 1000
    int idx = (int)floorf((norm + 1.0f) * 0.5f * (float)(NV - 1));
    idx = idx < 0 ? 0 : (idx > NV - 1 ? NV - 1 : idx);
    return idx;
}

// ---------------- kernel 1: streaming sum-of-exp, no atomics ----------------
__global__ __launch_bounds__(THREADS)
void sumexp_kernel(const float* __restrict__ vol) {
    const int blk  = blockIdx.x;
    const int pair = blk / SPLIT;
    const int part = blk % SPLIT;
    const int t    = threadIdx.x;

    const float4* p = reinterpret_cast<const float4*>(
        vol + (size_t)pair * VOX + (size_t)part * CHUNK) + t;

    float s0 = 0.0f, s1 = 0.0f;
#pragma unroll
    for (int i = 0; i < ITERS; ++i) {
        float4 v = __ldg(p + i * THREADS);
        s0 += __expf(v.x) + __expf(v.y);
        s1 += __expf(v.z) + __expf(v.w);
    }
    float s = s0 + s1;

#pragma unroll
    for (int off = 16; off > 0; off >>= 1)
        s += __shfl_down_sync(0xFFFFFFFFu, s, off);

    __shared__ float sh[THREADS / 32];
    const int lane = t & 31;
    const int wid  = t >> 5;
    if (lane == 0) sh[wid] = s;
    __syncthreads();

    if (t == 0) {
        float v = 0.0f;
#pragma unroll
        for (int k = 0; k < THREADS / 32; ++k) v += sh[k];
        g_partials[blk] = v;     // plain store; kernel boundary orders it
    }
}

// ---------------- kernel 2: parallel finalize, one block per pair ----------------
__global__ __launch_bounds__(32)
void finalize_kernel(const float* __restrict__ vol,
                     const float* __restrict__ label,
                     const float* __restrict__ center,
                     float* __restrict__ out) {
    const int pair = blockIdx.x;     // 0..NPAIR-1
    const int lane = threadIdx.x;

    // gather this pair's SPLIT partials (lanes 0..SPLIT-1)
    float v = (lane < SPLIT) ? g_partials[pair * SPLIT + lane] : 0.0f;
#pragma unroll
    for (int off = 16; off > 0; off >>= 1)
        v += __shfl_down_sync(0xFFFFFFFFu, v, off);

    if (lane == 0) {
        const int b = pair / NJ;
        const float cx = __ldg(center + b * 3 + 0);
        const float cy = __ldg(center + b * 3 + 1);
        const float cz = __ldg(center + b * 3 + 2);
        const float lx = __ldg(label + pair * 3 + 0);
        const float ly = __ldg(label + pair * 3 + 1);
        const float lz = __ldg(label + pair * 3 + 2);

        const int ix = grid_idx(lx, cx);
        const int iy = grid_idx(ly, cy);
        const int iz = grid_idx(lz, cz);
        const int flat = (ix * NV + iy) * NV + iz;

        const float x = __ldg(vol + (size_t)pair * VOX + flat);
        const float pprob = __expf(x) / v;
        const float term = -logf(pprob + 1e-6f) * (0.01f / (float)NPAIR);

        atomicAdd(&g_loss, term);
        __threadfence();
        unsigned int pd = atomicAdd(&g_pairs_done, 1u);
        if (pd == NPAIR - 1) {
            __threadfence();
            out[0] = atomicAdd(&g_loss, 0.0f);   // coherent read of final sum
            g_loss = 0.0f;                       // reset for next graph replay
            g_pairs_done = 0u;
            __threadfence();
        }
    }
}

extern "C" void kernel_launch(void* const* d_in, const int* in_sizes, int n_in,
                              void* d_out, int out_size) {
    const float* vol    = (const float*)d_in[0];
    const float* label  = (const float*)d_in[1];
    const float* center = (const float*)d_in[2];
    float* out = (float*)d_out;

    sumexp_kernel<<<NBLOCKS, THREADS>>>(vol);
    finalize_kernel<<<NPAIR, 32>>>(vol, label, center, out);
}

// round 8
// speedup vs baseline: 1.0719x; 1.0719x over previous
#include <cuda_runtime.h>
#include <math.h>

#define NB 8
#define NJ 17
#define NV 64
#define NPAIR (NB * NJ)             // 136
#define VOX (NV * NV * NV)          // 262144 elems = 1 MiB per pair
#define SPLIT 16
#define NBLOCKS (NPAIR * SPLIT)     // 2176
#define THREADS 256
#define CHUNK (VOX / SPLIT)         // 16384 elements per block
#define ITERS (CHUNK / 4 / THREADS) // 16 float4 per thread

__device__ float g_partials[NBLOCKS];   // rewritten every launch; no reset needed

__device__ __forceinline__ int grid_idx(float l, float c) {
    float norm = (l - c) * (1.0f / 1000.0f);        // box_range = 1000
    int idx = (int)floorf((norm + 1.0f) * 0.5f * (float)(NV - 1));
    idx = idx < 0 ? 0 : (idx > NV - 1 ? NV - 1 : idx);
    return idx;
}

// ---------------- kernel 1: streaming sum-of-exp ----------------
__global__ __launch_bounds__(THREADS)
void sumexp_kernel(const float* __restrict__ vol) {
    const int blk  = blockIdx.x;
    const int pair = blk / SPLIT;
    const int part = blk % SPLIT;
    const int t    = threadIdx.x;

    const float4* p = reinterpret_cast<const float4*>(
        vol + (size_t)pair * VOX + (size_t)part * CHUNK) + t;

    float s0 = 0.0f, s1 = 0.0f;
#pragma unroll
    for (int i = 0; i < ITERS; ++i) {
        float4 v = __ldg(p + i * THREADS);
        s0 += __expf(v.x) + __expf(v.y);
        s1 += __expf(v.z) + __expf(v.w);
    }
    float s = s0 + s1;

#pragma unroll
    for (int off = 16; off > 0; off >>= 1)
        s += __shfl_down_sync(0xFFFFFFFFu, s, off);

    __shared__ float sh[THREADS / 32];
    const int lane = t & 31;
    const int wid  = t >> 5;
    if (lane == 0) sh[wid] = s;
    __syncthreads();

    if (t == 0) {
        float v = 0.0f;
#pragma unroll
        for (int k = 0; k < THREADS / 32; ++k) v += sh[k];
        g_partials[blk] = v;
        // writes above are visible to the dependent grid after its griddepcontrol.wait
        asm volatile("griddepcontrol.launch_dependents;" ::: "memory");
    }
}

// ---------------- kernel 2: PDL finalize, one block, no atomics ----------------
__global__ __launch_bounds__(256)
void finalize_kernel(const float* __restrict__ vol,
                     const float* __restrict__ label,
                     const float* __restrict__ center,
                     float* __restrict__ out) {
    const int t = threadIdx.x;
    __shared__ float shr[256];

    // launched early via PDL; block until primary grid's partials are visible
    asm volatile("griddepcontrol.wait;" ::: "memory");

    float term = 0.0f;
    if (t < NPAIR) {
        float S = 0.0f;
#pragma unroll
        for (int k = 0; k < SPLIT; ++k)
            S += g_partials[t * SPLIT + k];

        const int b = t / NJ;
        const float cx = __ldg(center + b * 3 + 0);
        const float cy = __ldg(center + b * 3 + 1);
        const float cz = __ldg(center + b * 3 + 2);
        const float lx = __ldg(label + t * 3 + 0);
        const float ly = __ldg(label + t * 3 + 1);
        const float lz = __ldg(label + t * 3 + 2);

        const int ix = grid_idx(lx, cx);
        const int iy = grid_idx(ly, cy);
        const int iz = grid_idx(lz, cz);
        const int flat = (ix * NV + iy) * NV + iz;

        const float x = __ldg(vol + (size_t)t * VOX + flat);
        const float pprob = __expf(x) / S;
        term = -logf(pprob + 1e-6f) * (0.01f / (float)NPAIR);
    }
    shr[t] = term;
    __syncthreads();
#pragma unroll
    for (int sdist = 128; sdist > 0; sdist >>= 1) {
        if (t < sdist) shr[t] += shr[t + sdist];
        __syncthreads();
    }
    if (t == 0) out[0] = shr[0];
}

extern "C" void kernel_launch(void* const* d_in, const int* in_sizes, int n_in,
                              void* d_out, int out_size) {
    const float* vol    = (const float*)d_in[0];
    const float* label  = (const float*)d_in[1];
    const float* center = (const float*)d_in[2];
    float* out = (float*)d_out;

    sumexp_kernel<<<NBLOCKS, THREADS>>>(vol);

    // secondary launch with Programmatic Stream Serialization (PDL)
    cudaLaunchAttribute attrs[1];
    attrs[0].id = cudaLaunchAttributeProgrammaticStreamSerialization;
    attrs[0].val.programmaticStreamSerializationAllowed = 1;

    cudaLaunchConfig_t cfg = {};
    cfg.gridDim  = dim3(1, 1, 1);
    cfg.blockDim = dim3(256, 1, 1);
    cfg.dynamicSmemBytes = 0;
    cfg.stream = 0;                 // same (capture) stream as the primary
    cfg.attrs = attrs;
    cfg.numAttrs = 1;

    cudaLaunchKernelEx(&cfg, finalize_kernel, vol, label, center, out);
}

// round 9
// speedup vs baseline: 1.0958x; 1.0223x over previous
#include <cuda_runtime.h>
#include <math.h>

#define NB 8
#define NJ 17
#define NV 64
#define NPAIR (NB * NJ)             // 136
#define VOX (NV * NV * NV)          // 262144 elems = 1 MiB per pair
#define SPLIT 16
#define NBLOCKS (NPAIR * SPLIT)     // 2176
#define THREADS 256
#define CHUNK (VOX / SPLIT)         // 16384 elements per block
#define ITERS (CHUNK / 4 / THREADS) // 16 float4 per thread

__device__ float g_pairsum[NPAIR];  // red.add target; reset by finalize each launch
__device__ float g_picked[NPAIR];   // plain store by the one matching block per pair

__device__ __forceinline__ int grid_idx(float l, float c) {
    float norm = (l - c) * (1.0f / 1000.0f);        // box_range = 1000
    int idx = (int)floorf((norm + 1.0f) * 0.5f * (float)(NV - 1));
    idx = idx < 0 ? 0 : (idx > NV - 1 ? NV - 1 : idx);
    return idx;
}

// ---------------- kernel 1: streaming sum-of-exp + in-scan voxel pick ----------------
__global__ __launch_bounds__(THREADS)
void sumexp_kernel(const float* __restrict__ vol,
                   const float* __restrict__ label,
                   const float* __restrict__ center) {
    const int blk  = blockIdx.x;
    const int pair = blk / SPLIT;
    const int part = blk % SPLIT;
    const int t    = threadIdx.x;

    const float4* p = reinterpret_cast<const float4*>(
        vol + (size_t)pair * VOX + (size_t)part * CHUNK) + t;

    float s0 = 0.0f, s1 = 0.0f;
#pragma unroll
    for (int i = 0; i < ITERS; ++i) {
        float4 v = __ldg(p + i * THREADS);
        s0 += __expf(v.x) + __expf(v.y);
        s1 += __expf(v.z) + __expf(v.w);
    }
    float s = s0 + s1;

#pragma unroll
    for (int off = 16; off > 0; off >>= 1)
        s += __shfl_down_sync(0xFFFFFFFFu, s, off);

    __shared__ float sh[THREADS / 32];
    const int lane = t & 31;
    const int wid  = t >> 5;
    if (lane == 0) sh[wid] = s;
    __syncthreads();

    if (t == 0) {
        float v = 0.0f;
#pragma unroll
        for (int k = 0; k < THREADS / 32; ++k) v += sh[k];
        atomicAdd(&g_pairsum[pair], v);   // result unused -> REDG (no return stall)

        // --- voxel pick: does this block's chunk contain the GT voxel? ---
        const int b = pair / NJ;
        const float cx = __ldg(center + b * 3 + 0);
        const float cy = __ldg(center + b * 3 + 1);
        const float cz = __ldg(center + b * 3 + 2);
        const float lx = __ldg(label + pair * 3 + 0);
        const float ly = __ldg(label + pair * 3 + 1);
        const float lz = __ldg(label + pair * 3 + 2);
        const int ix = grid_idx(lx, cx);
        const int iy = grid_idx(ly, cy);
        const int iz = grid_idx(lz, cz);
        const int flat = (ix * NV + iy) * NV + iz;
        if (flat >= part * CHUNK && flat < (part + 1) * CHUNK) {
            // cache line just streamed by this block -> L1/L2 hit
            g_picked[pair] = __ldg(vol + (size_t)pair * VOX + flat);
        }

        __threadfence();  // make red.add + picked store visible to dependent grid
        asm volatile("griddepcontrol.launch_dependents;" ::: "memory");
    }
}

// ---------------- kernel 2: PDL finalize, trivial post-wait chain ----------------
__global__ __launch_bounds__(256)
void finalize_kernel(float* __restrict__ out) {
    const int t = threadIdx.x;
    __shared__ float shr[256];

    asm volatile("griddepcontrol.wait;" ::: "memory");

    float term = 0.0f;
    if (t < NPAIR) {
        const float S = g_pairsum[t];   // L2-hot (just red.add'ed)
        const float x = g_picked[t];    // L2-hot (just stored)
        const float pprob = __expf(x) / S;
        term = -logf(pprob + 1e-6f) * (0.01f / (float)NPAIR);
        g_pairsum[t] = 0.0f;            // reset for next graph replay
    }
    shr[t] = term;
    __syncthreads();
#pragma unroll
    for (int sdist = 128; sdist > 0; sdist >>= 1) {
        if (t < sdist) shr[t] += shr[t + sdist];
        __syncthreads();
    }
    if (t == 0) out[0] = shr[0];
}

extern "C" void kernel_launch(void* const* d_in, const int* in_sizes, int n_in,
                              void* d_out, int out_size) {
    const float* vol    = (const float*)d_in[0];
    const float* label  = (const float*)d_in[1];
    const float* center = (const float*)d_in[2];
    float* out = (float*)d_out;

    sumexp_kernel<<<NBLOCKS, THREADS>>>(vol, label, center);

    cudaLaunchAttribute attrs[1];
    attrs[0].id = cudaLaunchAttributeProgrammaticStreamSerialization;
    attrs[0].val.programmaticStreamSerializationAllowed = 1;

    cudaLaunchConfig_t cfg = {};
    cfg.gridDim  = dim3(1, 1, 1);
    cfg.blockDim = dim3(256, 1, 1);
    cfg.dynamicSmemBytes = 0;
    cfg.stream = 0;
    cfg.attrs = attrs;
    cfg.numAttrs = 1;

    cudaLaunchKernelEx(&cfg, finalize_kernel, out);
}